// round 6
// baseline (speedup 1.0000x reference)
#include <cuda_runtime.h>

typedef unsigned long long ull;

#define DIM 512
#define NX  1024
#define NY  1024

// Scratch (allocation-free rule: static __device__ arrays)
__device__ float g_hx[NX * DIM];
__device__ float g_hy[NY * DIM];

// ---------- packed f32x2 helpers ----------
__device__ __forceinline__ ull f2_fma(ull a, ull b, ull c) {
    ull r;
    asm("fma.rn.f32x2 %0, %1, %2, %3;" : "=l"(r) : "l"(a), "l"(b), "l"(c));
    return r;
}
__device__ __forceinline__ ull f2_add(ull a, ull b) {
    ull r;
    asm("add.rn.f32x2 %0, %1, %2;" : "=l"(r) : "l"(a), "l"(b));
    return r;
}
__device__ __forceinline__ ull f2_relu(ull s) {
    float lo, hi;
    asm("mov.b64 {%0, %1}, %2;" : "=f"(lo), "=f"(hi) : "l"(s));
    lo = fmaxf(lo, 0.0f);
    hi = fmaxf(hi, 0.0f);
    ull r;
    asm("mov.b64 %0, {%1, %2};" : "=l"(r) : "f"(lo), "f"(hi));
    return r;
}
__device__ __forceinline__ float f2_sum(ull s) {
    float lo, hi;
    asm("mov.b64 {%0, %1}, %2;" : "=f"(lo), "=f"(hi) : "l"(s));
    return lo + hi;
}

// ============================================================================
// Phase 1: hx = x @ W1[:DIM], hy = y @ W1[DIM:]   (z = 0 / 1)
// CTA tile 32(i) x 64(k), Dc = 16, 128 threads, thread tile 4x4, double-buffered.
// 512 CTAs -> all SMs busy, 3-4 CTAs/SM resident, fma-pipe-bound inner loop.
// ============================================================================
__global__ void __launch_bounds__(128, 6) gemm_kernel(
    const float* __restrict__ x, const float* __restrict__ y,
    const float* __restrict__ W1)
{
    __shared__ float2 xsp[2][8][33];  // [buf][d-pair][i 0..31]
    __shared__ float2 wsp[2][8][65];  // [buf][d-pair][k 0..63]

    const int z = blockIdx.z;
    const float* src = z ? y : x;
    const float* W   = W1 + z * (DIM * DIM);
    float* dst       = z ? g_hy : g_hx;

    const int tid = threadIdx.x;
    const int tx  = tid & 15;   // k lane (0..15)
    const int ty  = tid >> 4;   // i lane (0..7)
    const int i0  = blockIdx.y * 32;
    const int k0  = blockIdx.x * 64;

    // x tile: 32 rows x 16 d = 128 float4, 1/thread
    const int xrow = tid >> 2, xc4 = tid & 3;
    // W tile: 16 d-rows x 64 k = 256 float4, 2/thread
    const int wrow = tid >> 4, wc4 = tid & 15;   // t=0: rows 0..7; t=1: rows 8..15

    const float* xg = src + (i0 + xrow) * DIM + xc4 * 4;   // +16 per iter
    const float* wg = W + wrow * DIM + k0 + wc4 * 4;       // +16*DIM per iter

    float4 px  = *(const float4*)xg;
    float4 pw0 = *(const float4*)wg;
    float4 pw1 = *(const float4*)(wg + 8 * DIM);

    ull acc[4][4] = {};

    const int NIT = DIM / 16;
    for (int it = 0; it < NIT; ++it) {
        const int cur = it & 1;
        // store prefetched chunk into smem[cur]
        xsp[cur][xc4 * 2 + 0][xrow] = make_float2(px.x, px.y);
        xsp[cur][xc4 * 2 + 1][xrow] = make_float2(px.z, px.w);
        {
            float* wb0 = (float*)&wsp[cur][wrow >> 1][0] + (wrow & 1);
            wb0[(wc4 * 4 + 0) * 2] = pw0.x;
            wb0[(wc4 * 4 + 1) * 2] = pw0.y;
            wb0[(wc4 * 4 + 2) * 2] = pw0.z;
            wb0[(wc4 * 4 + 3) * 2] = pw0.w;
            float* wb1 = (float*)&wsp[cur][(wrow + 8) >> 1][0] + ((wrow + 8) & 1);
            wb1[(wc4 * 4 + 0) * 2] = pw1.x;
            wb1[(wc4 * 4 + 1) * 2] = pw1.y;
            wb1[(wc4 * 4 + 2) * 2] = pw1.z;
            wb1[(wc4 * 4 + 3) * 2] = pw1.w;
        }
        // prefetch next chunk (lands while we compute)
        if (it + 1 < NIT) {
            px  = *(const float4*)(xg + (it + 1) * 16);
            pw0 = *(const float4*)(wg + (it + 1) * 16 * DIM);
            pw1 = *(const float4*)(wg + (it + 1) * 16 * DIM + 8 * DIM);
        }
        __syncthreads();
        #pragma unroll
        for (int dp = 0; dp < 8; ++dp) {
            ull ap[4], bp[4];
            #pragma unroll
            for (int q = 0; q < 4; ++q)
                ap[q] = *(const ull*)&xsp[cur][dp][ty + 8 * q];    // broadcast
            #pragma unroll
            for (int q = 0; q < 4; ++q)
                bp[q] = *(const ull*)&wsp[cur][dp][tx + 16 * q];   // lane-contiguous
            #pragma unroll
            for (int a = 0; a < 4; ++a)
                #pragma unroll
                for (int b = 0; b < 4; ++b)
                    acc[a][b] = f2_fma(ap[a], bp[b], acc[a][b]);
        }
        __syncthreads();   // protects smem[cur] reuse two iterations later
    }
    #pragma unroll
    for (int a = 0; a < 4; ++a)
        #pragma unroll
        for (int b = 0; b < 4; ++b)
            dst[(i0 + ty + 8 * a) * DIM + k0 + tx + 16 * b] = f2_sum(acc[a][b]);
}

// ============================================================================
// Phase 2: out[i,j] = sum_k w2[k] * relu(hx[i,k] + hy[j,k])
// CTA tile 32(i) x 32(j), Kc = 32, 128 threads, thread tile 2x4, double-buffered.
// 1024 CTAs x 4 warps = 4096 warps -> ~28 warps/SM, single wave, balance 7/6.92.
// ============================================================================
__global__ void __launch_bounds__(128, 8) pair_kernel(
    const float* __restrict__ W2, float* __restrict__ out)
{
    __shared__ float2 hxs[2][16][33];   // [buf][k-pair][i 0..31]
    __shared__ float2 hys[2][16][33];   // [buf][k-pair][j 0..31]
    __shared__ float2 w2s[DIM / 2];

    const int tid = threadIdx.x;
    const int tx  = tid & 7;    // j lane (0..7)
    const int ty  = tid >> 3;   // i lane (0..15)
    const int i0  = blockIdx.y * 32;
    const int j0  = blockIdx.x * 32;

    w2s[tid]       = ((const float2*)W2)[tid];
    w2s[tid + 128] = ((const float2*)W2)[tid + 128];

    // tile loads: 32 rows x 8 float4-cols = 256 float4 each; 2/thread
    const int hr0 = tid >> 3;          // t=0 row (0..15); t=1: +16
    const int hc4 = tid & 7;
    const float* hxg = g_hx + (i0 + hr0) * DIM + hc4 * 4;
    const float* hyg = g_hy + (j0 + hr0) * DIM + hc4 * 4;

    float4 pxa = *(const float4*)hxg;
    float4 pxb = *(const float4*)(hxg + 16 * DIM);
    float4 pya = *(const float4*)hyg;
    float4 pyb = *(const float4*)(hyg + 16 * DIM);

    ull acc[2][4] = {};

    const int NIT = DIM / 32;
    for (int it = 0; it < NIT; ++it) {
        const int cur = it & 1;
        // store prefetched chunk into smem[cur]
        hxs[cur][hc4 * 2 + 0][hr0]      = make_float2(pxa.x, pxa.y);
        hxs[cur][hc4 * 2 + 1][hr0]      = make_float2(pxa.z, pxa.w);
        hxs[cur][hc4 * 2 + 0][hr0 + 16] = make_float2(pxb.x, pxb.y);
        hxs[cur][hc4 * 2 + 1][hr0 + 16] = make_float2(pxb.z, pxb.w);
        hys[cur][hc4 * 2 + 0][hr0]      = make_float2(pya.x, pya.y);
        hys[cur][hc4 * 2 + 1][hr0]      = make_float2(pya.z, pya.w);
        hys[cur][hc4 * 2 + 0][hr0 + 16] = make_float2(pyb.x, pyb.y);
        hys[cur][hc4 * 2 + 1][hr0 + 16] = make_float2(pyb.z, pyb.w);
        // prefetch next chunk
        if (it + 1 < NIT) {
            const int off = (it + 1) * 32;
            pxa = *(const float4*)(hxg + off);
            pxb = *(const float4*)(hxg + off + 16 * DIM);
            pya = *(const float4*)(hyg + off);
            pyb = *(const float4*)(hyg + off + 16 * DIM);
        }
        __syncthreads();
        #pragma unroll 4
        for (int dp = 0; dp < 16; ++dp) {
            ull w2k = *(const ull*)&w2s[it * 16 + dp];
            ull ap[2], bp[4];
            ap[0] = *(const ull*)&hxs[cur][dp][ty];        // broadcast
            ap[1] = *(const ull*)&hxs[cur][dp][ty + 16];
            #pragma unroll
            for (int q = 0; q < 4; ++q)
                bp[q] = *(const ull*)&hys[cur][dp][tx + 8 * q];  // lane-contiguous
            #pragma unroll
            for (int a = 0; a < 2; ++a)
                #pragma unroll
                for (int b = 0; b < 4; ++b)
                    acc[a][b] = f2_fma(f2_relu(f2_add(ap[a], bp[b])), w2k, acc[a][b]);
        }
        __syncthreads();   // protects smem[cur] reuse two iterations later
    }

    #pragma unroll
    for (int a = 0; a < 2; ++a)
        #pragma unroll
        for (int b = 0; b < 4; ++b)
            out[(i0 + ty + 16 * a) * NY + (j0 + tx + 8 * b)] = f2_sum(acc[a][b]);
}

extern "C" void kernel_launch(void* const* d_in, const int* in_sizes, int n_in,
                              void* d_out, int out_size) {
    const float* x  = (const float*)d_in[0];
    const float* y  = (const float*)d_in[1];
    const float* W1 = (const float*)d_in[2];
    const float* W2 = (const float*)d_in[3];
    // d_in[4] = is_pairwise (int32) — dataset fixes it to 0 (out_size == NX*NY)
    float* out = (float*)d_out;

    dim3 g1(DIM / 64, NX / 32, 2);    // 8 x 32 x 2 = 512 CTAs, 128 thr
    gemm_kernel<<<g1, 128>>>(x, y, W1);

    dim3 g2(NY / 32, NX / 32);        // 32 x 32 = 1024 CTAs, 128 thr
    pair_kernel<<<g2, 128>>>(W2, out);
}

// round 8
// speedup vs baseline: 1.0653x; 1.0653x over previous
#include <cuda_runtime.h>

typedef unsigned long long ull;

#define DIM 512
#define NX  1024
#define NY  1024

// Scratch (allocation-free rule: static __device__ arrays)
__device__ float g_hx[NX * DIM];
__device__ float g_hy[NY * DIM];

// ---------- packed f32x2 helpers ----------
__device__ __forceinline__ ull f2_fma(ull a, ull b, ull c) {
    ull r;
    asm("fma.rn.f32x2 %0, %1, %2, %3;" : "=l"(r) : "l"(a), "l"(b), "l"(c));
    return r;
}
__device__ __forceinline__ ull f2_add(ull a, ull b) {
    ull r;
    asm("add.rn.f32x2 %0, %1, %2;" : "=l"(r) : "l"(a), "l"(b));
    return r;
}
__device__ __forceinline__ ull f2_relu(ull s) {
    float lo, hi;
    asm("mov.b64 {%0, %1}, %2;" : "=f"(lo), "=f"(hi) : "l"(s));
    lo = fmaxf(lo, 0.0f);
    hi = fmaxf(hi, 0.0f);
    ull r;
    asm("mov.b64 %0, {%1, %2};" : "=l"(r) : "f"(lo), "f"(hi));
    return r;
}
__device__ __forceinline__ float f2_sum(ull s) {
    float lo, hi;
    asm("mov.b64 {%0, %1}, %2;" : "=f"(lo), "=f"(hi) : "l"(s));
    return lo + hi;
}

// ============================================================================
// Phase 1: hx = x @ W1[:DIM], hy = y @ W1[DIM:]   (z = 0 / 1)
// CTA tile 64(i) x 64(k), Dc = 32, 256 threads, thread tile 4x4, double-buffered.
// Kc=32 halves barrier count vs Dc=16; inner loop is fma-pipe-bound.
// ============================================================================
__global__ void __launch_bounds__(256, 3) gemm_kernel(
    const float* __restrict__ x, const float* __restrict__ y,
    const float* __restrict__ W1)
{
    __shared__ float2 xsp[2][16][65];  // [buf][d-pair][i 0..63]
    __shared__ float2 wsp[2][16][65];  // [buf][d-pair][k 0..63]

    const int z = blockIdx.z;
    const float* src = z ? y : x;
    const float* W   = W1 + z * (DIM * DIM);
    float* dst       = z ? g_hy : g_hx;

    const int tid = threadIdx.x;
    const int tx  = tid & 15;   // k lane (0..15)
    const int ty  = tid >> 4;   // i lane (0..15)
    const int i0  = blockIdx.y * 64;
    const int k0  = blockIdx.x * 64;

    // x chunk: 64 rows x 32 d = 512 float4; 2/thread (rows r, r+32)
    const int xrow = tid >> 3, xc4 = tid & 7;
    // W chunk: 32 d-rows x 64 k = 512 float4; 2/thread (rows r, r+16)
    const int wrow = tid >> 4, wc4 = tid & 15;

    const float* xg = src + (i0 + xrow) * DIM + xc4 * 4;   // +32 per iter
    const float* wg = W + wrow * DIM + k0 + wc4 * 4;       // +32*DIM per iter

    float4 px0 = *(const float4*)xg;
    float4 px1 = *(const float4*)(xg + 32 * DIM);
    float4 pw0 = *(const float4*)wg;
    float4 pw1 = *(const float4*)(wg + 16 * DIM);

    ull acc[4][4] = {};

    const int NIT = DIM / 32;
    for (int it = 0; it < NIT; ++it) {
        const int cur = it & 1;
        // store prefetched chunk into smem[cur]
        xsp[cur][xc4 * 2 + 0][xrow]      = make_float2(px0.x, px0.y);
        xsp[cur][xc4 * 2 + 1][xrow]      = make_float2(px0.z, px0.w);
        xsp[cur][xc4 * 2 + 0][xrow + 32] = make_float2(px1.x, px1.y);
        xsp[cur][xc4 * 2 + 1][xrow + 32] = make_float2(px1.z, px1.w);
        {
            float* wb0 = (float*)&wsp[cur][wrow >> 1][0] + (wrow & 1);
            wb0[(wc4 * 4 + 0) * 2] = pw0.x;
            wb0[(wc4 * 4 + 1) * 2] = pw0.y;
            wb0[(wc4 * 4 + 2) * 2] = pw0.z;
            wb0[(wc4 * 4 + 3) * 2] = pw0.w;
            float* wb1 = (float*)&wsp[cur][(wrow >> 1) + 8][0] + (wrow & 1);
            wb1[(wc4 * 4 + 0) * 2] = pw1.x;
            wb1[(wc4 * 4 + 1) * 2] = pw1.y;
            wb1[(wc4 * 4 + 2) * 2] = pw1.z;
            wb1[(wc4 * 4 + 3) * 2] = pw1.w;
        }
        // prefetch next chunk (lands while we compute)
        if (it + 1 < NIT) {
            const int xo = (it + 1) * 32;
            px0 = *(const float4*)(xg + xo);
            px1 = *(const float4*)(xg + xo + 32 * DIM);
            pw0 = *(const float4*)(wg + xo * DIM);
            pw1 = *(const float4*)(wg + xo * DIM + 16 * DIM);
        }
        __syncthreads();
        #pragma unroll 4
        for (int dp = 0; dp < 16; ++dp) {
            ull ap[4], bp[4];
            #pragma unroll
            for (int q = 0; q < 4; ++q)
                ap[q] = *(const ull*)&xsp[cur][dp][ty + 16 * q];   // broadcast
            #pragma unroll
            for (int q = 0; q < 4; ++q)
                bp[q] = *(const ull*)&wsp[cur][dp][tx + 16 * q];   // lane-contiguous
            #pragma unroll
            for (int a = 0; a < 4; ++a)
                #pragma unroll
                for (int b = 0; b < 4; ++b)
                    acc[a][b] = f2_fma(ap[a], bp[b], acc[a][b]);
        }
        __syncthreads();
    }
    #pragma unroll
    for (int a = 0; a < 4; ++a)
        #pragma unroll
        for (int b = 0; b < 4; ++b)
            dst[(i0 + ty + 16 * a) * DIM + k0 + tx + 16 * b] = f2_sum(acc[a][b]);
}

// ============================================================================
// Phase 2: out[i,j] = sum_k w2[k] * relu(hx[i,k] + hy[j,k])
// CTA tile 64(i) x 32(j), Kc = 32, 128 threads, thread tile 4x4, double-buffered.
// 512 CTAs -> 3.46 CTAs/SM (min 12 warps/SM): balanced waves, R5's LDS ratio.
// ============================================================================
__global__ void __launch_bounds__(128, 4) pair_kernel(
    const float* __restrict__ W2, float* __restrict__ out)
{
    __shared__ float2 hxs[2][16][65];   // [buf][k-pair][i 0..63]
    __shared__ float2 hys[2][16][33];   // [buf][k-pair][j 0..31]
    __shared__ float2 w2s[DIM / 2];

    const int tid = threadIdx.x;
    const int tx  = tid & 7;    // j lane (0..7)
    const int ty  = tid >> 3;   // i lane (0..15)
    const int i0  = blockIdx.y * 64;
    const int j0  = blockIdx.x * 32;

    w2s[tid]       = ((const float2*)W2)[tid];
    w2s[tid + 128] = ((const float2*)W2)[tid + 128];

    // hx chunk: 64 rows x 32 k = 512 float4; 4/thread (rows r,+16,+32,+48)
    // hy chunk: 32 rows x 32 k = 256 float4; 2/thread (rows r,+16)
    const int hr  = tid >> 3;          // 0..15
    const int hc4 = tid & 7;
    const float* hxg = g_hx + (i0 + hr) * DIM + hc4 * 4;
    const float* hyg = g_hy + (j0 + hr) * DIM + hc4 * 4;

    float4 pxa = *(const float4*)hxg;
    float4 pxb = *(const float4*)(hxg + 16 * DIM);
    float4 pxc = *(const float4*)(hxg + 32 * DIM);
    float4 pxd = *(const float4*)(hxg + 48 * DIM);
    float4 pya = *(const float4*)hyg;
    float4 pyb = *(const float4*)(hyg + 16 * DIM);

    ull acc[4][4] = {};

    const int NIT = DIM / 32;
    for (int it = 0; it < NIT; ++it) {
        const int cur = it & 1;
        // store prefetched chunk into smem[cur]
        hxs[cur][hc4 * 2 + 0][hr]      = make_float2(pxa.x, pxa.y);
        hxs[cur][hc4 * 2 + 1][hr]      = make_float2(pxa.z, pxa.w);
        hxs[cur][hc4 * 2 + 0][hr + 16] = make_float2(pxb.x, pxb.y);
        hxs[cur][hc4 * 2 + 1][hr + 16] = make_float2(pxb.z, pxb.w);
        hxs[cur][hc4 * 2 + 0][hr + 32] = make_float2(pxc.x, pxc.y);
        hxs[cur][hc4 * 2 + 1][hr + 32] = make_float2(pxc.z, pxc.w);
        hxs[cur][hc4 * 2 + 0][hr + 48] = make_float2(pxd.x, pxd.y);
        hxs[cur][hc4 * 2 + 1][hr + 48] = make_float2(pxd.z, pxd.w);
        hys[cur][hc4 * 2 + 0][hr]      = make_float2(pya.x, pya.y);
        hys[cur][hc4 * 2 + 1][hr]      = make_float2(pya.z, pya.w);
        hys[cur][hc4 * 2 + 0][hr + 16] = make_float2(pyb.x, pyb.y);
        hys[cur][hc4 * 2 + 1][hr + 16] = make_float2(pyb.z, pyb.w);
        // prefetch next chunk
        if (it + 1 < NIT) {
            const int off = (it + 1) * 32;
            pxa = *(const float4*)(hxg + off);
            pxb = *(const float4*)(hxg + off + 16 * DIM);
            pxc = *(const float4*)(hxg + off + 32 * DIM);
            pxd = *(const float4*)(hxg + off + 48 * DIM);
            pya = *(const float4*)(hyg + off);
            pyb = *(const float4*)(hyg + off + 16 * DIM);
        }
        __syncthreads();
        #pragma unroll 4
        for (int dp = 0; dp < 16; ++dp) {
            ull w2k = *(const ull*)&w2s[it * 16 + dp];
            ull ap[4], bp[4];
            #pragma unroll
            for (int q = 0; q < 4; ++q)
                ap[q] = *(const ull*)&hxs[cur][dp][ty + 16 * q];  // broadcast
            #pragma unroll
            for (int q = 0; q < 4; ++q)
                bp[q] = *(const ull*)&hys[cur][dp][tx + 8 * q];   // lane-contiguous
            #pragma unroll
            for (int a = 0; a < 4; ++a)
                #pragma unroll
                for (int b = 0; b < 4; ++b)
                    acc[a][b] = f2_fma(f2_relu(f2_add(ap[a], bp[b])), w2k, acc[a][b]);
        }
        __syncthreads();
    }

    #pragma unroll
    for (int a = 0; a < 4; ++a)
        #pragma unroll
        for (int b = 0; b < 4; ++b)
            out[(i0 + ty + 16 * a) * NY + (j0 + tx + 8 * b)] = f2_sum(acc[a][b]);
}

extern "C" void kernel_launch(void* const* d_in, const int* in_sizes, int n_in,
                              void* d_out, int out_size) {
    const float* x  = (const float*)d_in[0];
    const float* y  = (const float*)d_in[1];
    const float* W1 = (const float*)d_in[2];
    const float* W2 = (const float*)d_in[3];
    // d_in[4] = is_pairwise (int32) — dataset fixes it to 0 (out_size == NX*NY)
    float* out = (float*)d_out;

    dim3 g1(DIM / 64, NX / 64, 2);    // 8 x 16 x 2 = 256 CTAs, 256 thr
    gemm_kernel<<<g1, 256>>>(x, y, W1);

    dim3 g2(NY / 32, NX / 64);        // 32 x 16 = 512 CTAs, 128 thr
    pair_kernel<<<g2, 128>>>(W2, out);
}